// round 7
// baseline (speedup 1.0000x reference)
#include <cuda_runtime.h>

// Problem constants
#define Bn    4
#define Cc    256
#define HF    128
#define WF    128
#define Sx    64
#define CROPS_ELEMS ((size_t)128 * Cc * Sx * Sx)   // 134217728

// Scratch: feat transposed to NHWC [b][y][x][c], c contiguous (67 MB)
__device__ float g_nhwc[(size_t)Bn * HF * WF * Cc];

__device__ __forceinline__ void roi_params(const float* __restrict__ obb, int r,
                                           float& cx, float& cy, float& wf, float& hf,
                                           float& c_, float& s_) {
    const float* o = obb + r * 5;
    cx = o[0] * 0.125f;
    cy = o[1] * 0.125f;
    wf = fmaxf(o[2], 1.0f) * (1.25f / 8.0f);
    hf = fmaxf(o[3], 1.0f) * (1.25f / 8.0f);
    float ang = o[4] * 0.017453292519943295f;  // deg2rad
    c_ = cosf(ang);
    s_ = sinf(ang);
}

// ---------------------------------------------------------------------------
// Kernel 1: NCHW -> NHWC transpose, 4 y-rows per block (MLP=4).
// Block (8,32): tx = x-float4 chunk, ty = channel. grid (4, 8, 128):
// z encodes (b, y-quad). Per thread: 4 indep LDG.128, 1 sync, 4 STG.128.
// ---------------------------------------------------------------------------
__global__ __launch_bounds__(256) void transpose_kernel(const float* __restrict__ feat)
{
    __shared__ float ts[4][32 * 33];
    const int tx = threadIdx.x;       // 0..7
    const int ty = threadIdx.y;       // 0..31
    const int bz = blockIdx.z;        // 0..127
    const int b = bz >> 5;
    const int ybase = (bz & 31) * 4;

    const int c = blockIdx.y * 32 + ty;
    const float4* feat4 = reinterpret_cast<const float4*>(feat);
    const size_t rowbase = (size_t)(b * Cc + c) * HF;

    float4 v[4];
    #pragma unroll
    for (int k = 0; k < 4; ++k)
        v[k] = __ldcs(&feat4[(rowbase + ybase + k) * (WF / 4) + blockIdx.x * 8 + tx]);

    #pragma unroll
    for (int k = 0; k < 4; ++k) {
        ts[k][(4 * tx + 0) * 33 + ty] = v[k].x;
        ts[k][(4 * tx + 1) * 33 + ty] = v[k].y;
        ts[k][(4 * tx + 2) * 33 + ty] = v[k].z;
        ts[k][(4 * tx + 3) * 33 + ty] = v[k].w;
    }
    __syncthreads();

    float4* nh4 = reinterpret_cast<float4*>(g_nhwc);
    const int x = blockIdx.x * 32 + ty;
    #pragma unroll
    for (int k = 0; k < 4; ++k) {
        float4 o;
        o.x = ts[k][ty * 33 + 4 * tx + 0];
        o.y = ts[k][ty * 33 + 4 * tx + 1];
        o.z = ts[k][ty * 33 + 4 * tx + 2];
        o.w = ts[k][ty * 33 + 4 * tx + 3];
        nh4[((size_t)(b * HF + ybase + k) * WF + x) * (Cc / 4) + blockIdx.y * 8 + tx] = o;
    }
}

// ---------------------------------------------------------------------------
// Pipelined tap-reuse compute for one 128-channel slab (8 points per warp).
// Registers c00..c11 arrive preloaded for point ibase.
// ---------------------------------------------------------------------------
__device__ __forceinline__ void compute_slab(
    const float4* __restrict__ nhwc4,
    const int* o00, const int* o01, const int* o10, const int* o11,
    const float* w00s, const float* w01s, const float* w10s, const float* w11s,
    float* tile, int ibase, int co, int lane,
    int p00, int p01, int p10, int p11,
    float4 c00, float4 c01, float4 c10, float4 c11)
{
    #pragma unroll
    for (int j = 0; j < 8; ++j) {
        const int i = ibase + j;

        float4 n00, n01, n10, n11;
        int mode = 0;
        if (j < 7) {
            const int u00 = o00[i + 1], u01 = o01[i + 1];
            const int u10 = o10[i + 1], u11 = o11[i + 1];
            if (u00 == p00 && u01 == p01 && u10 == p10 && u11 == p11) {
                mode = 0;
            } else if (u00 == p01 && u10 == p11) {
                n01 = __ldg(&nhwc4[u01 + co]);
                n11 = __ldg(&nhwc4[u11 + co]);
                mode = 1;
            } else if (u00 == p10 && u01 == p11) {
                n10 = __ldg(&nhwc4[u10 + co]);
                n11 = __ldg(&nhwc4[u11 + co]);
                mode = 2;
            } else {
                n00 = __ldg(&nhwc4[u00 + co]);
                n01 = __ldg(&nhwc4[u01 + co]);
                n10 = __ldg(&nhwc4[u10 + co]);
                n11 = __ldg(&nhwc4[u11 + co]);
                mode = 3;
            }
            p00 = u00; p01 = u01; p10 = u10; p11 = u11;
        }

        const float a = w00s[i], b_ = w01s[i], c2 = w10s[i], d = w11s[i];
        float4 v;
        v.x = fmaf(d, c11.x, fmaf(c2, c10.x, fmaf(b_, c01.x, a * c00.x)));
        v.y = fmaf(d, c11.y, fmaf(c2, c10.y, fmaf(b_, c01.y, a * c00.y)));
        v.z = fmaf(d, c11.z, fmaf(c2, c10.z, fmaf(b_, c01.z, a * c00.z)));
        v.w = fmaf(d, c11.w, fmaf(c2, c10.w, fmaf(b_, c01.w, a * c00.w)));
        *reinterpret_cast<float4*>(&tile[i * 132 + 4 * lane]) = v;

        if (j < 7) {
            if (mode == 1)      { c00 = c01; c10 = c11; c01 = n01; c11 = n11; }
            else if (mode == 2) { c00 = c10; c01 = c11; c10 = n10; c11 = n11; }
            else if (mode == 3) { c00 = n00; c01 = n01; c10 = n10; c11 = n11; }
        }
    }
}

__device__ __forceinline__ void store_slab(
    const float* tile, float* __restrict__ out,
    int r, int sy, int slab, int sx_st, int cg)
{
    #pragma unroll
    for (int j = 0; j < 8; ++j) {
        const int chunk = cg * 8 + j;          // 0..31
        float4 v = *reinterpret_cast<const float4*>(&tile[sx_st * 132 + 4 * chunk]);
        const int c_global = slab * 128 + 4 * chunk;
        float* op = out + (((size_t)(r * Cc + c_global) * Sx + sy) * Sx) + sx_st;
        __stcs(op,               v.x);
        __stcs(op + 1 * Sx * Sx, v.y);
        __stcs(op + 2 * Sx * Sx, v.z);
        __stcs(op + 3 * Sx * Sx, v.w);
    }
}

// ---------------------------------------------------------------------------
// Kernel 2: pooling + M_all. One block per (roi, sy): 256 threads.
// Dynamic smem: offsets/weights (2KB) + double-buffered tile (2 x 33KB).
// Schedule: compute0 | sync | prefetch1 + store0 | compute1 | sync | store1.
// ---------------------------------------------------------------------------
__global__ __launch_bounds__(256) void rotated_roi_pool_kernel(
    const float* __restrict__ obb,
    float* __restrict__ out)
{
    extern __shared__ float dsm[];
    int*   o00  = reinterpret_cast<int*>(dsm);
    int*   o01  = o00 + Sx;
    int*   o10  = o01 + Sx;
    int*   o11  = o10 + Sx;
    float* w00s = dsm + 4 * Sx;
    float* w01s = w00s + Sx;
    float* w10s = w01s + Sx;
    float* w11s = w10s + Sx;
    float* tile0 = dsm + 8 * Sx;
    float* tile1 = tile0 + Sx * 132;

    const int t    = threadIdx.x;
    const int sy   = blockIdx.x;
    const int r    = blockIdx.y;
    const int b    = r >> 5;
    const int warp = t >> 5;
    const int lane = t & 31;

    // ---- Phase 0: per-sample-point coordinates ----
    if (t < Sx) {
        const int sx = t;
        float cx, cy, wf, hf, c_, s_;
        roi_params(obb, r, cx, cy, wf, hf, c_, s_);

        const float sxs = wf * (2.0f / (float)WF);
        const float sys = hf * (2.0f / (float)HF);
        const float txc = cx * (2.0f / (float)WF) - 1.0f;
        const float tyc = cy * (2.0f / (float)HF) - 1.0f;
        const float a11 = c_ * sxs, a12 = -s_ * sys;
        const float a21 = s_ * sxs, a22 =  c_ * sys;

        const float X = 2.0f * ((float)sx + 0.5f) / (float)Sx - 1.0f;
        const float Y = 2.0f * ((float)sy + 0.5f) / (float)Sx - 1.0f;

        const float gx = a11 * X + a12 * Y + txc;
        const float gy = a21 * X + a22 * Y + tyc;

        const float ix = ((gx + 1.0f) * (float)WF - 1.0f) * 0.5f;
        const float iy = ((gy + 1.0f) * (float)HF - 1.0f) * 0.5f;

        const float x0f = floorf(ix);
        const float y0f = floorf(iy);
        const float wx = ix - x0f;
        const float wy = iy - y0f;

        const int x0 = (int)x0f, y0 = (int)y0f;
        const int x1 = x0 + 1,   y1 = y0 + 1;

        const float vx0 = (x0 >= 0 && x0 < WF) ? 1.0f : 0.0f;
        const float vx1 = (x1 >= 0 && x1 < WF) ? 1.0f : 0.0f;
        const float vy0 = (y0 >= 0 && y0 < HF) ? 1.0f : 0.0f;
        const float vy1 = (y1 >= 0 && y1 < HF) ? 1.0f : 0.0f;

        w00s[sx] = (1.0f - wx) * (1.0f - wy) * vx0 * vy0;
        w01s[sx] = wx          * (1.0f - wy) * vx1 * vy0;
        w10s[sx] = (1.0f - wx) * wy          * vx0 * vy1;
        w11s[sx] = wx          * wy          * vx1 * vy1;

        const int xc0 = min(max(x0, 0), WF - 1);
        const int xc1 = min(max(x1, 0), WF - 1);
        const int yc0 = min(max(y0, 0), HF - 1);
        const int yc1 = min(max(y1, 0), HF - 1);

        const int base = b * HF * WF;  // pixels
        o00[sx] = (base + yc0 * WF + xc0) * (Cc / 4);
        o01[sx] = (base + yc0 * WF + xc1) * (Cc / 4);
        o10[sx] = (base + yc1 * WF + xc0) * (Cc / 4);
        o11[sx] = (base + yc1 * WF + xc1) * (Cc / 4);
    }
    __syncthreads();

    const float4* __restrict__ nhwc4 = reinterpret_cast<const float4*>(g_nhwc);
    const int sx_st = t & 63;
    const int cg    = t >> 6;
    const int ibase = warp * 8;

    // ---- slab 0 compute ----
    {
        const int co = lane;
        const int p00 = o00[ibase], p01 = o01[ibase], p10 = o10[ibase], p11 = o11[ibase];
        float4 c00 = __ldg(&nhwc4[p00 + co]);
        float4 c01 = __ldg(&nhwc4[p01 + co]);
        float4 c10 = __ldg(&nhwc4[p10 + co]);
        float4 c11 = __ldg(&nhwc4[p11 + co]);
        compute_slab(nhwc4, o00, o01, o10, o11, w00s, w01s, w10s, w11s,
                     tile0, ibase, co, lane, p00, p01, p10, p11, c00, c01, c10, c11);
    }
    __syncthreads();

    // ---- prefetch slab 1's first taps (fly during store0) ----
    const int co1 = 32 + lane;
    const int q00 = o00[ibase], q01 = o01[ibase], q10 = o10[ibase], q11 = o11[ibase];
    float4 d00 = __ldg(&nhwc4[q00 + co1]);
    float4 d01 = __ldg(&nhwc4[q01 + co1]);
    float4 d10 = __ldg(&nhwc4[q10 + co1]);
    float4 d11 = __ldg(&nhwc4[q11 + co1]);

    // ---- store slab 0 ----
    store_slab(tile0, out, r, sy, 0, sx_st, cg);

    // ---- slab 1 compute (no sync needed: writes tile1, store0 read tile0) ----
    compute_slab(nhwc4, o00, o01, o10, o11, w00s, w01s, w10s, w11s,
                 tile1, ibase, co1, lane, q00, q01, q10, q11, d00, d01, d10, d11);
    __syncthreads();

    // ---- store slab 1 ----
    store_slab(tile1, out, r, sy, 1, sx_st, cg);

    // ---- M_all (folded): block (sy==0, r), one thread ----
    if (sy == 0 && t == 0) {
        float cx, cy, wf, hf, c_, s_;
        roi_params(obb, r, cx, cy, wf, hf, c_, s_);
        const float A  =  c_ * (wf / (float)Sx);
        const float Bv = -s_ * (hf / (float)Sx);
        const float A2 =  s_ * (wf / (float)Sx);
        const float B2 =  c_ * (hf / (float)Sx);
        const float Cx = cx - 0.5f * (float)Sx * (A + Bv);
        const float Cy = cy - 0.5f * (float)Sx * (A2 + B2);
        float* o = out + CROPS_ELEMS + (size_t)r * 6;
        o[0] = A;  o[1] = Bv; o[2] = Cx;
        o[3] = A2; o[4] = B2; o[5] = Cy;
    }
}

extern "C" void kernel_launch(void* const* d_in, const int* in_sizes, int n_in,
                              void* d_out, int out_size) {
    const float* feat = (const float*)d_in[0];
    const float* obb  = (const float*)d_in[1];
    float* out = (float*)d_out;

    const int pool_smem = (8 * Sx + 2 * Sx * 132) * sizeof(float);  // ~68 KB
    cudaFuncSetAttribute(rotated_roi_pool_kernel,
                         cudaFuncAttributeMaxDynamicSharedMemorySize, pool_smem);

    dim3 tb(8, 32, 1);
    dim3 tg(WF / 32, Cc / 32, Bn * HF / 4);   // (4, 8, 128)
    transpose_kernel<<<tg, tb>>>(feat);

    dim3 grid(Sx, 128, 1);                    // (sy, roi)
    rotated_roi_pool_kernel<<<grid, 256, pool_smem>>>(obb, out);
}

// round 8
// speedup vs baseline: 1.1079x; 1.1079x over previous
#include <cuda_runtime.h>

// Problem constants
#define Bn    4
#define Cc    256
#define HF    128
#define WF    128
#define Sx    64
#define CROPS_ELEMS ((size_t)128 * Cc * Sx * Sx)   // 134217728

// Scratch: feat transposed to NHWC [b][y][x][c], c contiguous (67 MB)
__device__ float g_nhwc[(size_t)Bn * HF * WF * Cc];

__device__ __forceinline__ void roi_params(const float* __restrict__ obb, int r,
                                           float& cx, float& cy, float& wf, float& hf,
                                           float& c_, float& s_) {
    const float* o = obb + r * 5;
    cx = o[0] * 0.125f;
    cy = o[1] * 0.125f;
    wf = fmaxf(o[2], 1.0f) * (1.25f / 8.0f);
    hf = fmaxf(o[3], 1.0f) * (1.25f / 8.0f);
    float ang = o[4] * 0.017453292519943295f;  // deg2rad
    c_ = cosf(ang);
    s_ = sinf(ang);
}

// ---------------------------------------------------------------------------
// Kernel 1: NCHW -> NHWC transpose, 4 y-rows per block (MLP=4).
// ---------------------------------------------------------------------------
__global__ __launch_bounds__(256) void transpose_kernel(const float* __restrict__ feat)
{
    __shared__ float ts[4][32 * 33];
    const int tx = threadIdx.x;       // 0..7
    const int ty = threadIdx.y;       // 0..31
    const int bz = blockIdx.z;        // 0..127
    const int b = bz >> 5;
    const int ybase = (bz & 31) * 4;

    const int c = blockIdx.y * 32 + ty;
    const float4* feat4 = reinterpret_cast<const float4*>(feat);
    const size_t rowbase = (size_t)(b * Cc + c) * HF;

    float4 v[4];
    #pragma unroll
    for (int k = 0; k < 4; ++k)
        v[k] = __ldcs(&feat4[(rowbase + ybase + k) * (WF / 4) + blockIdx.x * 8 + tx]);

    #pragma unroll
    for (int k = 0; k < 4; ++k) {
        ts[k][(4 * tx + 0) * 33 + ty] = v[k].x;
        ts[k][(4 * tx + 1) * 33 + ty] = v[k].y;
        ts[k][(4 * tx + 2) * 33 + ty] = v[k].z;
        ts[k][(4 * tx + 3) * 33 + ty] = v[k].w;
    }
    __syncthreads();

    float4* nh4 = reinterpret_cast<float4*>(g_nhwc);
    const int x = blockIdx.x * 32 + ty;
    #pragma unroll
    for (int k = 0; k < 4; ++k) {
        float4 o;
        o.x = ts[k][ty * 33 + 4 * tx + 0];
        o.y = ts[k][ty * 33 + 4 * tx + 1];
        o.z = ts[k][ty * 33 + 4 * tx + 2];
        o.w = ts[k][ty * 33 + 4 * tx + 3];
        nh4[((size_t)(b * HF + ybase + k) * WF + x) * (Cc / 4) + blockIdx.y * 8 + tx] = o;
    }
}

// ---------------------------------------------------------------------------
// Kernel 2: pooling + M_all. One block per (roi, sy): 256 threads.
// Round-6 schedule (single tile, 36KB static smem) with launch_bounds(256,4)
// to cap registers at 64 -> 4 blocks/SM (occ 50%) instead of 3 (36%).
// ---------------------------------------------------------------------------
__global__ __launch_bounds__(256, 4) void rotated_roi_pool_kernel(
    const float* __restrict__ obb,
    float* __restrict__ out)
{
    __shared__ int   o00[Sx], o01[Sx], o10[Sx], o11[Sx];   // float4-unit pixel bases
    __shared__ float w00s[Sx], w01s[Sx], w10s[Sx], w11s[Sx];
    __shared__ float tile[Sx * 132];                       // [point][132] floats

    const int t    = threadIdx.x;
    const int sy   = blockIdx.x;
    const int r    = blockIdx.y;
    const int b    = r >> 5;
    const int warp = t >> 5;
    const int lane = t & 31;

    // ---- Phase 0: per-sample-point coordinates ----
    if (t < Sx) {
        const int sx = t;
        float cx, cy, wf, hf, c_, s_;
        roi_params(obb, r, cx, cy, wf, hf, c_, s_);

        const float sxs = wf * (2.0f / (float)WF);
        const float sys = hf * (2.0f / (float)HF);
        const float txc = cx * (2.0f / (float)WF) - 1.0f;
        const float tyc = cy * (2.0f / (float)HF) - 1.0f;
        const float a11 = c_ * sxs, a12 = -s_ * sys;
        const float a21 = s_ * sxs, a22 =  c_ * sys;

        const float X = 2.0f * ((float)sx + 0.5f) / (float)Sx - 1.0f;
        const float Y = 2.0f * ((float)sy + 0.5f) / (float)Sx - 1.0f;

        const float gx = a11 * X + a12 * Y + txc;
        const float gy = a21 * X + a22 * Y + tyc;

        const float ix = ((gx + 1.0f) * (float)WF - 1.0f) * 0.5f;
        const float iy = ((gy + 1.0f) * (float)HF - 1.0f) * 0.5f;

        const float x0f = floorf(ix);
        const float y0f = floorf(iy);
        const float wx = ix - x0f;
        const float wy = iy - y0f;

        const int x0 = (int)x0f, y0 = (int)y0f;
        const int x1 = x0 + 1,   y1 = y0 + 1;

        const float vx0 = (x0 >= 0 && x0 < WF) ? 1.0f : 0.0f;
        const float vx1 = (x1 >= 0 && x1 < WF) ? 1.0f : 0.0f;
        const float vy0 = (y0 >= 0 && y0 < HF) ? 1.0f : 0.0f;
        const float vy1 = (y1 >= 0 && y1 < HF) ? 1.0f : 0.0f;

        w00s[sx] = (1.0f - wx) * (1.0f - wy) * vx0 * vy0;
        w01s[sx] = wx          * (1.0f - wy) * vx1 * vy0;
        w10s[sx] = (1.0f - wx) * wy          * vx0 * vy1;
        w11s[sx] = wx          * wy          * vx1 * vy1;

        const int xc0 = min(max(x0, 0), WF - 1);
        const int xc1 = min(max(x1, 0), WF - 1);
        const int yc0 = min(max(y0, 0), HF - 1);
        const int yc1 = min(max(y1, 0), HF - 1);

        const int base = b * HF * WF;  // pixels
        o00[sx] = (base + yc0 * WF + xc0) * (Cc / 4);
        o01[sx] = (base + yc0 * WF + xc1) * (Cc / 4);
        o10[sx] = (base + yc1 * WF + xc0) * (Cc / 4);
        o11[sx] = (base + yc1 * WF + xc1) * (Cc / 4);
    }
    __syncthreads();

    const float4* __restrict__ nhwc4 = reinterpret_cast<const float4*>(g_nhwc);
    const int sx_st = t & 63;   // store-phase sx
    const int cg    = t >> 6;   // store-phase channel group (0..3)
    const int ibase = warp * 8;

    #pragma unroll
    for (int slab = 0; slab < 2; ++slab) {
        const int co = slab * 32 + lane;  // float4 chunk within pixel

        // ---- compute phase: pipelined tap-reuse ----
        int p00 = o00[ibase], p01 = o01[ibase], p10 = o10[ibase], p11 = o11[ibase];
        float4 c00 = __ldg(&nhwc4[p00 + co]);
        float4 c01 = __ldg(&nhwc4[p01 + co]);
        float4 c10 = __ldg(&nhwc4[p10 + co]);
        float4 c11 = __ldg(&nhwc4[p11 + co]);

        #pragma unroll
        for (int j = 0; j < 8; ++j) {
            const int i = ibase + j;

            // Issue loads for point i+1 (consumed next iteration)
            float4 n00, n01, n10, n11;
            int mode = 0;
            if (j < 7) {
                const int u00 = o00[i + 1], u01 = o01[i + 1];
                const int u10 = o10[i + 1], u11 = o11[i + 1];
                if (u00 == p00 && u01 == p01 && u10 == p10 && u11 == p11) {
                    mode = 0;
                } else if (u00 == p01 && u10 == p11) {
                    n01 = __ldg(&nhwc4[u01 + co]);
                    n11 = __ldg(&nhwc4[u11 + co]);
                    mode = 1;
                } else if (u00 == p10 && u01 == p11) {
                    n10 = __ldg(&nhwc4[u10 + co]);
                    n11 = __ldg(&nhwc4[u11 + co]);
                    mode = 2;
                } else {
                    n00 = __ldg(&nhwc4[u00 + co]);
                    n01 = __ldg(&nhwc4[u01 + co]);
                    n10 = __ldg(&nhwc4[u10 + co]);
                    n11 = __ldg(&nhwc4[u11 + co]);
                    mode = 3;
                }
                p00 = u00; p01 = u01; p10 = u10; p11 = u11;
            }

            const float a = w00s[i], b_ = w01s[i], c2 = w10s[i], d = w11s[i];
            float4 v;
            v.x = fmaf(d, c11.x, fmaf(c2, c10.x, fmaf(b_, c01.x, a * c00.x)));
            v.y = fmaf(d, c11.y, fmaf(c2, c10.y, fmaf(b_, c01.y, a * c00.y)));
            v.z = fmaf(d, c11.z, fmaf(c2, c10.z, fmaf(b_, c01.z, a * c00.z)));
            v.w = fmaf(d, c11.w, fmaf(c2, c10.w, fmaf(b_, c01.w, a * c00.w)));
            *reinterpret_cast<float4*>(&tile[i * 132 + 4 * lane]) = v;

            if (j < 7) {
                if (mode == 1)      { c00 = c01; c10 = c11; c01 = n01; c11 = n11; }
                else if (mode == 2) { c00 = c10; c01 = c11; c10 = n10; c11 = n11; }
                else if (mode == 3) { c00 = n00; c01 = n01; c10 = n10; c11 = n11; }
            }
        }
        __syncthreads();

        // ---- store phase: lanes = sx, coalesced streaming stores ----
        #pragma unroll
        for (int j = 0; j < 8; ++j) {
            const int chunk = cg * 8 + j;          // 0..31
            float4 v = *reinterpret_cast<const float4*>(&tile[sx_st * 132 + 4 * chunk]);
            const int c_global = slab * 128 + 4 * chunk;
            float* op = out + (((size_t)(r * Cc + c_global) * Sx + sy) * Sx) + sx_st;
            __stcs(op,               v.x);
            __stcs(op + 1 * Sx * Sx, v.y);
            __stcs(op + 2 * Sx * Sx, v.z);
            __stcs(op + 3 * Sx * Sx, v.w);
        }
        __syncthreads();
    }

    // ---- M_all (folded): block (sy==0, r), one thread ----
    if (sy == 0 && t == 0) {
        float cx, cy, wf, hf, c_, s_;
        roi_params(obb, r, cx, cy, wf, hf, c_, s_);
        const float A  =  c_ * (wf / (float)Sx);
        const float Bv = -s_ * (hf / (float)Sx);
        const float A2 =  s_ * (wf / (float)Sx);
        const float B2 =  c_ * (hf / (float)Sx);
        const float Cx = cx - 0.5f * (float)Sx * (A + Bv);
        const float Cy = cy - 0.5f * (float)Sx * (A2 + B2);
        float* o = out + CROPS_ELEMS + (size_t)r * 6;
        o[0] = A;  o[1] = Bv; o[2] = Cx;
        o[3] = A2; o[4] = B2; o[5] = Cy;
    }
}

extern "C" void kernel_launch(void* const* d_in, const int* in_sizes, int n_in,
                              void* d_out, int out_size) {
    const float* feat = (const float*)d_in[0];
    const float* obb  = (const float*)d_in[1];
    float* out = (float*)d_out;

    dim3 tb(8, 32, 1);
    dim3 tg(WF / 32, Cc / 32, Bn * HF / 4);   // (4, 8, 128)
    transpose_kernel<<<tg, tb>>>(feat);

    dim3 grid(Sx, 128, 1);                    // (sy, roi)
    rotated_roi_pool_kernel<<<grid, 256>>>(obb, out);
}